// round 5
// baseline (speedup 1.0000x reference)
#include <cuda_runtime.h>

#define N_NODES 100000
#define N_EDGES 3200000
#define N_FEAT  512
#define N_HID   16
#define N_CLS   7

#define SCAN_BLK   1024
#define SCAN_GRID  98            // 98*1024 = 100352 >= N_NODES

// Scratch (device globals; no allocation allowed)
__device__ __align__(128) float g_h   [N_NODES * N_HID];  // x @ W1
__device__ __align__(128) float g_h2  [N_NODES * 8];      // relu(agg1+b1) @ W2, padded
__device__ __align__(128) int   g_deg [SCAN_GRID * SCAN_BLK];  // per-dst degree
__device__ __align__(128) int   g_off [SCAN_GRID * SCAN_BLK];  // CSR offsets (excl scan)
__device__ __align__(128) int   g_cur [N_NODES];               // fill cursors
__device__ __align__(128) int   g_srcs[N_EDGES];               // CSR: src ids grouped by dst
__device__ int g_bsum [SCAN_GRID];
__device__ int g_bsumo[SCAN_GRID];

typedef unsigned long long u64;

__device__ __forceinline__ u64 pack2(float a, float b) {
    u64 r; asm("mov.b64 %0, {%1,%2};" : "=l"(r) : "f"(a), "f"(b)); return r;
}
__device__ __forceinline__ void unpack2(u64 v, float& a, float& b) {
    asm("mov.b64 {%0,%1}, %2;" : "=f"(a), "=f"(b) : "l"(v));
}
__device__ __forceinline__ void ffma2(u64& d, u64 a, u64 b) {
    asm("fma.rn.f32x2 %0, %1, %2, %0;" : "+l"(d) : "l"(a), "l"(b));
}
__device__ __forceinline__ void fadd2(u64& d, u64 a) {
    asm("add.rn.f32x2 %0, %0, %1;" : "+l"(d) : "l"(a));
}

// ---------------------------------------------------------------- zero counters
__global__ void init_kernel() {
    int stride = gridDim.x * blockDim.x;
    int i = blockIdx.x * blockDim.x + threadIdx.x;
    for (int j = i; j < SCAN_GRID * SCAN_BLK; j += stride) g_deg[j] = 0;
    for (int j = i; j < N_NODES; j += stride) g_cur[j] = 0;
}

// ---------------------------------------------------------------- degree histogram
__global__ void hist_kernel(const int* __restrict__ ei) {
    int e = blockIdx.x * blockDim.x + threadIdx.x;
    if (e >= N_EDGES) return;
    atomicAdd(&g_deg[ei[N_EDGES + e]], 1);
}

// ---------------------------------------------------------------- scan (3 phases, deterministic)
__global__ void scan1_kernel() {
    __shared__ int sd[SCAN_BLK];
    int t = threadIdx.x, b = blockIdx.x;
    int g = b * SCAN_BLK + t;
    int val = g_deg[g];
    sd[t] = val;
    __syncthreads();
    for (int d = 1; d < SCAN_BLK; d <<= 1) {
        int tmp = 0;
        if (t >= d) tmp = sd[t - d];
        __syncthreads();
        if (t >= d) sd[t] += tmp;
        __syncthreads();
    }
    int incl = sd[t];
    g_off[g] = incl - val;                 // exclusive
    if (t == SCAN_BLK - 1) g_bsum[b] = incl;
}

__global__ void scan2_kernel() {
    __shared__ int sd[128];
    int t = threadIdx.x;
    int val = (t < SCAN_GRID) ? g_bsum[t] : 0;
    sd[t] = val;
    __syncthreads();
    for (int d = 1; d < 128; d <<= 1) {
        int tmp = 0;
        if (t >= d) tmp = sd[t - d];
        __syncthreads();
        if (t >= d) sd[t] += tmp;
        __syncthreads();
    }
    if (t < SCAN_GRID) g_bsumo[t] = sd[t] - val;   // exclusive
}

__global__ void scan3_kernel() {
    int g = blockIdx.x * blockDim.x + threadIdx.x;
    if (g < N_NODES) g_off[g] += g_bsumo[g >> 10];
}

// ---------------------------------------------------------------- CSR fill
__global__ void fill_kernel(const int* __restrict__ ei) {
    int e = blockIdx.x * blockDim.x + threadIdx.x;
    if (e >= N_EDGES) return;
    int src = ei[e];
    int dst = ei[N_EDGES + e];
    int pos = atomicAdd(&g_cur[dst], 1);
    g_srcs[g_off[dst] + pos] = src;
}

// ---------------------------------------------------------------- GEMM1: h = x @ W1
__global__ void __launch_bounds__(256, 2)
gemm1_kernel(const float* __restrict__ x, const float* __restrict__ W1) {
    __shared__ float4 xs[256];   // 2 rows * 512 floats, XOR-swizzled
    const int tid = threadIdx.x;
    const int w = tid >> 5, l = tid & 31;
    const int q = w & 3, s = w >> 2;

    u64 wr0[16], wr1[16];
#pragma unroll
    for (int j = 0; j < 16; j++) {
        float4 wv = *reinterpret_cast<const float4*>(W1 + (l * 16 + j) * 16 + q * 4);
        wr0[j] = pack2(wv.x, wv.y);
        wr1[j] = pack2(wv.z, wv.w);
    }

    float4* h4 = reinterpret_cast<float4*>(g_h);
    const int swz_t = tid ^ ((tid >> 3) & 7);
    const int g0 = s * 128 + l * 4;

    for (int p = blockIdx.x; p < N_NODES / 2; p += gridDim.x) {
        float4 v = reinterpret_cast<const float4*>(x)[(size_t)p * 256 + tid];
        __syncthreads();
        xs[swz_t] = v;
        __syncthreads();

        u64 a0 = 0ull, a1 = 0ull;
#pragma unroll
        for (int i = 0; i < 4; i++) {
            int g = g0 + i;
            float4 xv = xs[g ^ ((g >> 3) & 7)];
            u64 xx;
            xx = pack2(xv.x, xv.x); ffma2(a0, xx, wr0[4*i+0]); ffma2(a1, xx, wr1[4*i+0]);
            xx = pack2(xv.y, xv.y); ffma2(a0, xx, wr0[4*i+1]); ffma2(a1, xx, wr1[4*i+1]);
            xx = pack2(xv.z, xv.z); ffma2(a0, xx, wr0[4*i+2]); ffma2(a1, xx, wr1[4*i+2]);
            xx = pack2(xv.w, xv.w); ffma2(a0, xx, wr0[4*i+3]); ffma2(a1, xx, wr1[4*i+3]);
        }
#pragma unroll
        for (int off = 16; off; off >>= 1) {
            u64 t0 = __shfl_down_sync(0xffffffffu, a0, off);
            u64 t1 = __shfl_down_sync(0xffffffffu, a1, off);
            fadd2(a0, t0); fadd2(a1, t1);
        }
        if (l == 0) {
            float4 o;
            unpack2(a0, o.x, o.y);
            unpack2(a1, o.z, o.w);
            h4[(2 * p + s) * 4 + q] = o;
        }
    }
}

// ---------------------------------------------------------------- gather1 + fused transform2
// warp per node: agg1 = sum h[src]; h2 = relu(agg1+b1) @ W2, written to g_h2.
// Lane = c*8 + j: chunk c (float4, 4 feats), edge-slot j (stride 8).
__global__ void __launch_bounds__(256, 8)
gather1_kernel(const float* __restrict__ W2, const float* __restrict__ b1) {
    const int lane = threadIdx.x & 31;
    const int wid  = threadIdx.x >> 5;
    const int c = lane >> 3, j = lane & 7;
    const int warp_global = blockIdx.x * 8 + wid;
    const int n_warps = gridDim.x * 8;

    // Per-lane W2 rows for this lane's chunk: k = 4c..4c+3, 7 cols each
    float w2r[4][7];
#pragma unroll
    for (int kk = 0; kk < 4; kk++)
#pragma unroll
        for (int cc = 0; cc < 7; cc++)
            w2r[kk][cc] = __ldg(W2 + (c * 4 + kk) * 7 + cc);
    float4 b1c = *reinterpret_cast<const float4*>(b1 + c * 4);

    const float4* h4 = reinterpret_cast<const float4*>(g_h);
    float4* h2_4 = reinterpret_cast<float4*>(g_h2);

    for (int n = warp_global; n < N_NODES; n += n_warps) {
        int start = g_off[n];
        int deg   = g_deg[n];
        int end   = start + deg;

        float4 acc = make_float4(0.f, 0.f, 0.f, 0.f);
        for (int i = start + j; i < end; i += 8) {
            int s = g_srcs[i];
            float4 v = h4[s * 4 + c];
            acc.x += v.x; acc.y += v.y; acc.z += v.z; acc.w += v.w;
        }
        // reduce across j within each 8-lane chunk group
#pragma unroll
        for (int d = 4; d; d >>= 1) {
            acc.x += __shfl_down_sync(0xffffffffu, acc.x, d, 8);
            acc.y += __shfl_down_sync(0xffffffffu, acc.y, d, 8);
            acc.z += __shfl_down_sync(0xffffffffu, acc.z, d, 8);
            acc.w += __shfl_down_sync(0xffffffffu, acc.w, d, 8);
        }
        // lanes j==0 (0,8,16,24) hold chunk sums. Fused transform:
        float r0 = fmaxf(acc.x + b1c.x, 0.f);
        float r1 = fmaxf(acc.y + b1c.y, 0.f);
        float r2 = fmaxf(acc.z + b1c.z, 0.f);
        float r3 = fmaxf(acc.w + b1c.w, 0.f);
        float po[7];
#pragma unroll
        for (int cc = 0; cc < 7; cc++) {
            float t = r0 * w2r[0][cc];
            t = fmaf(r1, w2r[1][cc], t);
            t = fmaf(r2, w2r[2][cc], t);
            t = fmaf(r3, w2r[3][cc], t);
            po[cc] = t;
        }
        // reduce partial outputs across the 4 chunk-holding lanes (0,8,16,24)
#pragma unroll
        for (int cc = 0; cc < 7; cc++) {
            po[cc] += __shfl_down_sync(0xffffffffu, po[cc], 16);
            po[cc] += __shfl_down_sync(0xffffffffu, po[cc], 8);
        }
        if (lane == 0) {
            h2_4[n * 2 + 0] = make_float4(po[0], po[1], po[2], po[3]);
            h2_4[n * 2 + 1] = make_float4(po[4], po[5], po[6], 0.f);
        }
    }
}

// ---------------------------------------------------------------- gather2 + fused log_softmax
// warp per node: agg2 = sum h2[src]; out = log_softmax(agg2 + b2).
// Lane = c*16 + j: chunk c (float4), edge-slot j (stride 16).
__global__ void __launch_bounds__(256, 8)
gather2_kernel(const float* __restrict__ b2, float* __restrict__ out) {
    const int lane = threadIdx.x & 31;
    const int wid  = threadIdx.x >> 5;
    const int c = lane >> 4, j = lane & 15;
    const int warp_global = blockIdx.x * 8 + wid;
    const int n_warps = gridDim.x * 8;

    float b2r[7];
#pragma unroll
    for (int cc = 0; cc < 7; cc++) b2r[cc] = __ldg(b2 + cc);

    const float4* h2_4 = reinterpret_cast<const float4*>(g_h2);

    for (int n = warp_global; n < N_NODES; n += n_warps) {
        int start = g_off[n];
        int deg   = g_deg[n];
        int end   = start + deg;

        float4 acc = make_float4(0.f, 0.f, 0.f, 0.f);
        for (int i = start + j; i < end; i += 16) {
            int s = g_srcs[i];
            float4 v = h2_4[s * 2 + c];
            acc.x += v.x; acc.y += v.y; acc.z += v.z; acc.w += v.w;
        }
#pragma unroll
        for (int d = 8; d; d >>= 1) {
            acc.x += __shfl_down_sync(0xffffffffu, acc.x, d, 16);
            acc.y += __shfl_down_sync(0xffffffffu, acc.y, d, 16);
            acc.z += __shfl_down_sync(0xffffffffu, acc.z, d, 16);
            acc.w += __shfl_down_sync(0xffffffffu, acc.w, d, 16);
        }
        // lane 0 holds feats 0-3, lane 16 holds feats 4-7; pull to lane 0
        float u4 = __shfl_down_sync(0xffffffffu, acc.x, 16);
        float u5 = __shfl_down_sync(0xffffffffu, acc.y, 16);
        float u6 = __shfl_down_sync(0xffffffffu, acc.z, 16);
        if (lane == 0) {
            float v[7];
            v[0] = acc.x + b2r[0];
            v[1] = acc.y + b2r[1];
            v[2] = acc.z + b2r[2];
            v[3] = acc.w + b2r[3];
            v[4] = u4 + b2r[4];
            v[5] = u5 + b2r[5];
            v[6] = u6 + b2r[6];
            float m = v[0];
#pragma unroll
            for (int cc = 1; cc < 7; cc++) m = fmaxf(m, v[cc]);
            float ssum = 0.f;
#pragma unroll
            for (int cc = 0; cc < 7; cc++) ssum += expf(v[cc] - m);
            float lse = m + logf(ssum);
            float* op = out + (size_t)n * 7;
#pragma unroll
            for (int cc = 0; cc < 7; cc++) op[cc] = v[cc] - lse;
        }
    }
}

// ----------------------------------------------------------------
// Inputs identified by element count (pairwise distinct):
//   x: 51,200,000  edge_index: 6,400,000  W1: 8,192  W2: 112  b1: 16  b2: 7
extern "C" void kernel_launch(void* const* d_in, const int* in_sizes, int n_in,
                              void* d_out, int out_size) {
    const float* x  = nullptr;
    const int*   ei = nullptr;
    const float* W1 = nullptr;
    const float* b1 = nullptr;
    const float* W2 = nullptr;
    const float* b2 = nullptr;

    for (int i = 0; i < n_in; i++) {
        switch (in_sizes[i]) {
            case N_NODES * N_FEAT: x  = (const float*)d_in[i]; break;
            case 2 * N_EDGES:      ei = (const int*)d_in[i];   break;
            case N_FEAT * N_HID:   W1 = (const float*)d_in[i]; break;
            case N_HID:            b1 = (const float*)d_in[i]; break;
            case N_HID * N_CLS:    W2 = (const float*)d_in[i]; break;
            case N_CLS:            b2 = (const float*)d_in[i]; break;
            default: break;
        }
    }
    float* out = (float*)d_out;

    init_kernel<<<148, 512>>>();
    hist_kernel<<<N_EDGES / 256, 256>>>(ei);
    scan1_kernel<<<SCAN_GRID, SCAN_BLK>>>();
    scan2_kernel<<<1, 128>>>();
    scan3_kernel<<<(N_NODES + 511) / 512, 512>>>();
    fill_kernel<<<N_EDGES / 256, 256>>>(ei);
    gemm1_kernel<<<296, 256>>>(x, W1);
    gather1_kernel<<<1184, 256>>>(W2, b1);
    gather2_kernel<<<1184, 256>>>(b2, out);
}

// round 6
// speedup vs baseline: 1.1383x; 1.1383x over previous
#include <cuda_runtime.h>

#define N_NODES 100000
#define N_EDGES 3200000
#define N_FEAT  512
#define N_HID   16
#define N_CLS   7

#define SCAN_BLK   1024
#define SCAN_GRID  98            // 98*1024 = 100352 >= N_NODES
#define SCAN_TOT   (SCAN_GRID * SCAN_BLK)

// Scratch (device globals; no allocation allowed)
__device__ __align__(128) float g_h   [N_NODES * N_HID];  // x @ W1
__device__ __align__(128) float g_h2  [N_NODES * 8];      // relu(agg1+b1) @ W2, padded
__device__ __align__(128) int   g_deg [SCAN_TOT];         // per-dst degree
__device__ __align__(128) int   g_off [SCAN_TOT];         // CSR offsets (exclusive scan)
__device__ __align__(128) int   g_pos [N_EDGES];          // within-segment position (from hist)
__device__ __align__(128) int   g_srcs[N_EDGES];          // CSR: src ids grouped by dst
__device__ int g_bsum [SCAN_GRID];
__device__ int g_bsumo[SCAN_GRID];

typedef unsigned long long u64;

__device__ __forceinline__ u64 pack2(float a, float b) {
    u64 r; asm("mov.b64 %0, {%1,%2};" : "=l"(r) : "f"(a), "f"(b)); return r;
}
__device__ __forceinline__ void unpack2(u64 v, float& a, float& b) {
    asm("mov.b64 {%0,%1}, %2;" : "=f"(a), "=f"(b) : "l"(v));
}
__device__ __forceinline__ void ffma2(u64& d, u64 a, u64 b) {
    asm("fma.rn.f32x2 %0, %1, %2, %0;" : "+l"(d) : "l"(a), "l"(b));
}
__device__ __forceinline__ void fadd2(u64& d, u64 a) {
    asm("add.rn.f32x2 %0, %0, %1;" : "+l"(d) : "l"(a));
}

// ---------------------------------------------------------------- zero degree counters
__global__ void init_kernel() {
    int stride = gridDim.x * blockDim.x;
    for (int j = blockIdx.x * blockDim.x + threadIdx.x; j < SCAN_TOT; j += stride)
        g_deg[j] = 0;
}

// ---------------------------------------------------------------- degree histogram (+position)
__global__ void hist_kernel(const int* __restrict__ ei) {
    int e = blockIdx.x * blockDim.x + threadIdx.x;
    if (e >= N_EDGES) return;
    int dst = ei[N_EDGES + e];
    g_pos[e] = atomicAdd(&g_deg[dst], 1);
}

// ---------------------------------------------------------------- scan (3 phases, deterministic)
__global__ void scan1_kernel() {
    __shared__ int sd[SCAN_BLK];
    int t = threadIdx.x, b = blockIdx.x;
    int g = b * SCAN_BLK + t;
    int val = g_deg[g];
    sd[t] = val;
    __syncthreads();
    for (int d = 1; d < SCAN_BLK; d <<= 1) {
        int tmp = 0;
        if (t >= d) tmp = sd[t - d];
        __syncthreads();
        if (t >= d) sd[t] += tmp;
        __syncthreads();
    }
    int incl = sd[t];
    g_off[g] = incl - val;                 // exclusive
    if (t == SCAN_BLK - 1) g_bsum[b] = incl;
}

__global__ void scan2_kernel() {
    __shared__ int sd[128];
    int t = threadIdx.x;
    int val = (t < SCAN_GRID) ? g_bsum[t] : 0;
    sd[t] = val;
    __syncthreads();
    for (int d = 1; d < 128; d <<= 1) {
        int tmp = 0;
        if (t >= d) tmp = sd[t - d];
        __syncthreads();
        if (t >= d) sd[t] += tmp;
        __syncthreads();
    }
    if (t < SCAN_GRID) g_bsumo[t] = sd[t] - val;   // exclusive
}

__global__ void scan3_kernel() {
    int g = blockIdx.x * blockDim.x + threadIdx.x;
    if (g < SCAN_TOT) g_off[g] += g_bsumo[g >> 10];
}

// ---------------------------------------------------------------- CSR fill (atomic-free)
__global__ void fill_kernel(const int* __restrict__ ei) {
    int e = blockIdx.x * blockDim.x + threadIdx.x;
    if (e >= N_EDGES) return;
    int src = ei[e];
    int dst = ei[N_EDGES + e];
    g_srcs[g_off[dst] + g_pos[e]] = src;
}

// ---------------------------------------------------------------- GEMM1: h = x @ W1
__global__ void __launch_bounds__(256, 2)
gemm1_kernel(const float* __restrict__ x, const float* __restrict__ W1) {
    __shared__ float4 xs[256];   // 2 rows * 512 floats, XOR-swizzled
    const int tid = threadIdx.x;
    const int w = tid >> 5, l = tid & 31;
    const int q = w & 3, s = w >> 2;

    u64 wr0[16], wr1[16];
#pragma unroll
    for (int j = 0; j < 16; j++) {
        float4 wv = *reinterpret_cast<const float4*>(W1 + (l * 16 + j) * 16 + q * 4);
        wr0[j] = pack2(wv.x, wv.y);
        wr1[j] = pack2(wv.z, wv.w);
    }

    float4* h4 = reinterpret_cast<float4*>(g_h);
    const int swz_t = tid ^ ((tid >> 3) & 7);
    const int g0 = s * 128 + l * 4;

    for (int p = blockIdx.x; p < N_NODES / 2; p += gridDim.x) {
        float4 v = reinterpret_cast<const float4*>(x)[(size_t)p * 256 + tid];
        __syncthreads();
        xs[swz_t] = v;
        __syncthreads();

        u64 a0 = 0ull, a1 = 0ull;
#pragma unroll
        for (int i = 0; i < 4; i++) {
            int g = g0 + i;
            float4 xv = xs[g ^ ((g >> 3) & 7)];
            u64 xx;
            xx = pack2(xv.x, xv.x); ffma2(a0, xx, wr0[4*i+0]); ffma2(a1, xx, wr1[4*i+0]);
            xx = pack2(xv.y, xv.y); ffma2(a0, xx, wr0[4*i+1]); ffma2(a1, xx, wr1[4*i+1]);
            xx = pack2(xv.z, xv.z); ffma2(a0, xx, wr0[4*i+2]); ffma2(a1, xx, wr1[4*i+2]);
            xx = pack2(xv.w, xv.w); ffma2(a0, xx, wr0[4*i+3]); ffma2(a1, xx, wr1[4*i+3]);
        }
#pragma unroll
        for (int off = 16; off; off >>= 1) {
            u64 t0 = __shfl_down_sync(0xffffffffu, a0, off);
            u64 t1 = __shfl_down_sync(0xffffffffu, a1, off);
            fadd2(a0, t0); fadd2(a1, t1);
        }
        if (l == 0) {
            float4 o;
            unpack2(a0, o.x, o.y);
            unpack2(a1, o.z, o.w);
            h4[(2 * p + s) * 4 + q] = o;
        }
    }
}

// ---------------------------------------------------------------- gather1 + fused relu/W2
// Warp per node. Lane = slot*16 + f: feature f in lane (coalesced 64B row reads),
// 2 edge slots. Unroll 4 with independent accumulators (MLP=4).
__global__ void __launch_bounds__(256, 8)
gather1_kernel(const float* __restrict__ W2, const float* __restrict__ b1) {
    const int lane = threadIdx.x & 31;
    const int wid  = threadIdx.x >> 5;
    const int f    = lane & 15;        // feature
    const int slot = lane >> 4;        // edge slot (0..1)
    const int warp_global = blockIdx.x * 8 + wid;
    const int n_warps = gridDim.x * 8;

    float w2r[7];
#pragma unroll
    for (int cc = 0; cc < 7; cc++) w2r[cc] = __ldg(W2 + f * 7 + cc);
    const float b1f = __ldg(b1 + f);

    for (int n = warp_global; n < N_NODES; n += n_warps) {
        const int start = g_off[n];
        const int end   = start + g_deg[n];

        float a0 = 0.f, a1 = 0.f, a2 = 0.f, a3 = 0.f;
        int i = start + slot;
        for (; i + 6 < end; i += 8) {
            int s0 = g_srcs[i];
            int s1 = g_srcs[i + 2];
            int s2 = g_srcs[i + 4];
            int s3 = g_srcs[i + 6];
            a0 += g_h[s0 * 16 + f];
            a1 += g_h[s1 * 16 + f];
            a2 += g_h[s2 * 16 + f];
            a3 += g_h[s3 * 16 + f];
        }
        for (; i < end; i += 2) a0 += g_h[g_srcs[i] * 16 + f];
        float acc = (a0 + a1) + (a2 + a3);
        acc += __shfl_xor_sync(0xffffffffu, acc, 16);   // sum the 2 slots

        // fused transform2: r_f in lane f (duplicated in both 16-halves)
        float r = fmaxf(acc + b1f, 0.f);
        float po[7];
#pragma unroll
        for (int cc = 0; cc < 7; cc++) po[cc] = r * w2r[cc];
#pragma unroll
        for (int d = 8; d; d >>= 1) {
#pragma unroll
            for (int cc = 0; cc < 7; cc++)
                po[cc] += __shfl_xor_sync(0xffffffffu, po[cc], d);
        }
        if (lane == 0) {
            float4* op = reinterpret_cast<float4*>(g_h2) + n * 2;
            op[0] = make_float4(po[0], po[1], po[2], po[3]);
            op[1] = make_float4(po[4], po[5], po[6], 0.f);
        }
    }
}

// ---------------------------------------------------------------- gather2 + fused log_softmax
// Warp per node. Lane = slot*8 + f: 8 features, 4 edge slots. Unroll 4.
__global__ void __launch_bounds__(256, 8)
gather2_kernel(const float* __restrict__ b2, float* __restrict__ out) {
    const int lane = threadIdx.x & 31;
    const int wid  = threadIdx.x >> 5;
    const int f    = lane & 7;
    const int slot = lane >> 3;        // 0..3
    const int warp_global = blockIdx.x * 8 + wid;
    const int n_warps = gridDim.x * 8;

    const float b2f = (f < 7) ? __ldg(b2 + f) : 0.f;

    for (int n = warp_global; n < N_NODES; n += n_warps) {
        const int start = g_off[n];
        const int end   = start + g_deg[n];

        float a0 = 0.f, a1 = 0.f, a2 = 0.f, a3 = 0.f;
        int i = start + slot;
        for (; i + 12 < end; i += 16) {
            int s0 = g_srcs[i];
            int s1 = g_srcs[i + 4];
            int s2 = g_srcs[i + 8];
            int s3 = g_srcs[i + 12];
            a0 += g_h2[s0 * 8 + f];
            a1 += g_h2[s1 * 8 + f];
            a2 += g_h2[s2 * 8 + f];
            a3 += g_h2[s3 * 8 + f];
        }
        for (; i < end; i += 4) a0 += g_h2[g_srcs[i] * 8 + f];
        float acc = (a0 + a1) + (a2 + a3);
        acc += __shfl_xor_sync(0xffffffffu, acc, 16);   // sum 4 slots
        acc += __shfl_xor_sync(0xffffffffu, acc, 8);

        // fused log_softmax across the 8 feature lanes (f=7 is padding)
        float v = acc + b2f;
        float m = (f < 7) ? v : -3.0e38f;
#pragma unroll
        for (int d = 4; d; d >>= 1) m = fmaxf(m, __shfl_xor_sync(0xffffffffu, m, d));
        float ex = (f < 7) ? expf(v - m) : 0.f;
        float ssum = ex;
#pragma unroll
        for (int d = 4; d; d >>= 1) ssum += __shfl_xor_sync(0xffffffffu, ssum, d);
        float lse = m + logf(ssum);
        if (slot == 0 && f < 7) out[(size_t)n * 7 + f] = v - lse;
    }
}

// ----------------------------------------------------------------
// Inputs identified by element count (pairwise distinct):
//   x: 51,200,000  edge_index: 6,400,000  W1: 8,192  W2: 112  b1: 16  b2: 7
extern "C" void kernel_launch(void* const* d_in, const int* in_sizes, int n_in,
                              void* d_out, int out_size) {
    const float* x  = nullptr;
    const int*   ei = nullptr;
    const float* W1 = nullptr;
    const float* b1 = nullptr;
    const float* W2 = nullptr;
    const float* b2 = nullptr;

    for (int i = 0; i < n_in; i++) {
        switch (in_sizes[i]) {
            case N_NODES * N_FEAT: x  = (const float*)d_in[i]; break;
            case 2 * N_EDGES:      ei = (const int*)d_in[i];   break;
            case N_FEAT * N_HID:   W1 = (const float*)d_in[i]; break;
            case N_HID:            b1 = (const float*)d_in[i]; break;
            case N_HID * N_CLS:    W2 = (const float*)d_in[i]; break;
            case N_CLS:            b2 = (const float*)d_in[i]; break;
            default: break;
        }
    }
    float* out = (float*)d_out;

    init_kernel<<<148, 512>>>();
    hist_kernel<<<N_EDGES / 256, 256>>>(ei);
    scan1_kernel<<<SCAN_GRID, SCAN_BLK>>>();
    scan2_kernel<<<1, 128>>>();
    scan3_kernel<<<(SCAN_TOT + 511) / 512, 512>>>();
    fill_kernel<<<N_EDGES / 256, 256>>>(ei);
    gemm1_kernel<<<296, 256>>>(x, W1);
    gather1_kernel<<<1184, 256>>>(W2, b1);
    gather2_kernel<<<1184, 256>>>(b2, out);
}